// round 16
// baseline (speedup 1.0000x reference)
#include <cuda_runtime.h>
#include <cuda_fp16.h>
#include <cstdint>

// RelationalPolicyHead, factored:
//   W1T fp16 pre-transposed once                      [k_prep]
//   P = emb @ U, Q = emb @ V + b1                     [k_node: persistent HMMA, A-reuse over both halves]
//   e_exp = exp( W2^T relu(P[src]+Q'[tgt]) + b2 )     [k_edge: pair/half-warp + fused sum + fused normalize]

#define EDGE_BLOCKS 592     // 148 SMs x 4 resident blocks: exactly one wave (spin-safe)
#define NODE_BLOCKS 296
#define MAX_NODES 100000
#define NSTR 136            // halves per smem row (272 B): conflict-free ldmatrix

__device__ __half g_Wt[2 * 128 * 128];   // [half][n][k] fp16
__device__ __half g_Ph[MAX_NODES * 128];
__device__ __half g_Qh[MAX_NODES * 128];
__device__ float  g_exps[1048576];
__device__ float  g_partials[EDGE_BLOCKS];
__device__ float  g_inv_total;
__device__ int    g_done = 0;

__device__ __forceinline__ uint32_t smem_u32(const void* p) {
    uint32_t a;
    asm("{ .reg .u64 t; cvta.to.shared.u64 t, %1; cvt.u32.u64 %0, t; }" : "=r"(a) : "l"(p));
    return a;
}

// ---------------- W1 -> fp16 transposed [h][n][k] ----------------
__global__ void k_prep(const float* __restrict__ W1) {
    int i = blockIdx.x * 256 + threadIdx.x;          // 32768
    int h = i >> 14, r = i & 16383;
    int n = r >> 7, k = r & 127;
    g_Wt[i] = __float2half_rn(W1[h * 16384 + k * 128 + n]);
}

// ---------------- node GEMM: persistent, both halves per block (A-reuse) ----------------
#define AS_HALVES (128 * NSTR)
#define NODE_SMEM ((3 * AS_HALVES) * 2 + 512)   // As + Bs[2] fp16 + b1f

__global__ __launch_bounds__(256, 2)
void k_node(const float* __restrict__ emb, const float* __restrict__ b1,
            int nodes, int ntiles) {
    extern __shared__ __half hsm[];
    __half* As = hsm;                     // [m][k] 128 x NSTR
    __half* Bs = hsm + AS_HALVES;         // [h][n][k] 2 x 128 x NSTR
    float*  b1f = (float*)(hsm + 3 * AS_HALVES);

    const int tid  = threadIdx.x;
    const int lane = tid & 31;
    const int w    = tid >> 5;
    const int t0   = blockIdx.x;

    // ---- load BOTH B halves once ----
    {
        const uint4* src = (const uint4*)g_Wt;
        #pragma unroll
        for (int it = 0; it < 16; it++) {
            int i = it * 256 + tid;            // uint4 index over 2x128x16
            int r = i >> 4, c8 = (i & 15) * 8; // r in 0..255 spans both halves
            *(uint4*)(Bs + r * NSTR + c8) = src[i];
        }
        if (tid < 128) b1f[tid] = b1[tid];
    }

    const uint32_t as_base = smem_u32(As);
    const int bmat = lane >> 3, bs_ = lane & 7;
    const uint32_t brow_off = (uint32_t)((((bmat >> 1) * 8 + bs_) * NSTR + (bmat & 1) * 8) * 2);
    const int arow = (lane & 7) + ((lane >> 3) & 1) * 8;
    const int acol8 = (lane >> 4) * 8;

    for (int t = t0; t < ntiles; t += NODE_BLOCKS) {
        const int m0 = t * 128;

        __syncthreads();   // previous tile's ldmatrix readers done before A overwrite
        #pragma unroll
        for (int it = 0; it < 16; it++) {
            int i4 = it * 256 + tid;
            int row = i4 >> 5, c4 = (i4 & 31) * 4;
            float4 v = make_float4(0.f, 0.f, 0.f, 0.f);
            if (m0 + row < nodes) v = ((const float4*)emb)[(size_t)(m0 + row) * 32 + (i4 & 31)];
            __half2 h01 = __floats2half2_rn(v.x, v.y);
            __half2 h23 = __floats2half2_rn(v.z, v.w);
            uint2 pk;
            pk.x = *(uint32_t*)&h01; pk.y = *(uint32_t*)&h23;
            *(uint2*)(As + row * NSTR + c4) = pk;
        }
        __syncthreads();

        #pragma unroll
        for (int h = 0; h < 2; h++) {
            const uint32_t bs_base = smem_u32(Bs + h * AS_HALVES);

            float acc[16][4];
            #pragma unroll
            for (int i = 0; i < 16; i++)
                #pragma unroll
                for (int j = 0; j < 4; j++) acc[i][j] = 0.f;

            #pragma unroll
            for (int kc = 0; kc < 8; kc++) {
                uint32_t a0, a1, a2, a3;
                uint32_t aaddr = as_base + (uint32_t)(((w * 16 + arow) * NSTR) + kc * 16 + acol8) * 2u;
                asm volatile("ldmatrix.sync.aligned.m8n8.x4.shared.b16 {%0,%1,%2,%3}, [%4];"
                             : "=r"(a0), "=r"(a1), "=r"(a2), "=r"(a3) : "r"(aaddr));
                #pragma unroll
                for (int g = 0; g < 8; g++) {
                    uint32_t baddr = bs_base + brow_off + (uint32_t)(g * 16 * NSTR + kc * 16) * 2u;
                    uint32_t b0, b1r, b2, b3;
                    asm volatile("ldmatrix.sync.aligned.m8n8.x4.shared.b16 {%0,%1,%2,%3}, [%4];"
                                 : "=r"(b0), "=r"(b1r), "=r"(b2), "=r"(b3) : "r"(baddr));
                    asm volatile(
                        "mma.sync.aligned.m16n8k16.row.col.f32.f16.f16.f32 "
                        "{%0,%1,%2,%3}, {%4,%5,%6,%7}, {%8,%9}, {%0,%1,%2,%3};"
                        : "+f"(acc[2*g][0]), "+f"(acc[2*g][1]), "+f"(acc[2*g][2]), "+f"(acc[2*g][3])
                        : "r"(a0), "r"(a1), "r"(a2), "r"(a3), "r"(b0), "r"(b1r));
                    asm volatile(
                        "mma.sync.aligned.m16n8k16.row.col.f32.f16.f16.f32 "
                        "{%0,%1,%2,%3}, {%4,%5,%6,%7}, {%8,%9}, {%0,%1,%2,%3};"
                        : "+f"(acc[2*g+1][0]), "+f"(acc[2*g+1][1]), "+f"(acc[2*g+1][2]), "+f"(acc[2*g+1][3])
                        : "r"(a0), "r"(a1), "r"(a2), "r"(a3), "r"(b2), "r"(b3));
                }
            }

            __half* out = h ? g_Qh : g_Ph;
            const int r0 = m0 + w * 16 + (lane >> 2);
            const int cb = (lane & 3) * 2;
            if (r0 < nodes) {
                #pragma unroll
                for (int n8 = 0; n8 < 16; n8++) {
                    float bx = h ? b1f[n8 * 8 + cb] : 0.f;
                    float by2 = h ? b1f[n8 * 8 + cb + 1] : 0.f;
                    __half2 hv = __floats2half2_rn(acc[n8][0] + bx, acc[n8][1] + by2);
                    *(uint32_t*)(out + (size_t)r0 * 128 + n8 * 8 + cb) = *(uint32_t*)&hv;
                }
            }
            if (r0 + 8 < nodes) {
                #pragma unroll
                for (int n8 = 0; n8 < 16; n8++) {
                    float bx = h ? b1f[n8 * 8 + cb] : 0.f;
                    float by2 = h ? b1f[n8 * 8 + cb + 1] : 0.f;
                    __half2 hv = __floats2half2_rn(acc[n8][2] + bx, acc[n8][3] + by2);
                    *(uint32_t*)(out + (size_t)(r0 + 8) * 128 + n8 * 8 + cb) = *(uint32_t*)&hv;
                }
            }
        }
    }
}

// ---------------- edge kernel: pair/half-warp, fused sum + fused normalize ----------------
__global__ __launch_bounds__(256, 4)
void k_edge(const int* __restrict__ lm, const float* __restrict__ W2,
            const float* __restrict__ b2, float4* __restrict__ out4, int E) {
    __shared__ float sdata[256];
    __shared__ int   is_last;
    const int tid    = threadIdx.x;
    const int lane   = tid & 31;
    const int lane16 = lane & 15;
    const int hw     = ((blockIdx.x * 256 + tid) >> 5) * 2 + (lane >> 4);
    const int nhw    = (EDGE_BLOCKS * 256) >> 4;

    const float4 w2a = ((const float4*)W2)[lane16 * 2];
    const float4 w2b = ((const float4*)W2)[lane16 * 2 + 1];
    const float  b2v = b2[0];
    const __half2 z  = __float2half2_rn(0.f);

    const int npairs = (E + 1) >> 1;
    float s = 0.f;
    for (int pi = hw; pi < npairs; pi += nhw) {
        const int e0 = pi * 2;
        const bool has1 = (e0 + 1) < E;

        int sn0 = lm[e0];
        int tn0 = lm[E + e0];
        int sn1 = has1 ? lm[e0 + 1] : sn0;
        int tn1 = has1 ? lm[E + e0 + 1] : tn0;

        uint4 pv0 = *(const uint4*)(g_Ph + (size_t)sn0 * 128 + lane16 * 8);
        uint4 qv0 = *(const uint4*)(g_Qh + (size_t)tn0 * 128 + lane16 * 8);
        uint4 pv1 = *(const uint4*)(g_Ph + (size_t)sn1 * 128 + lane16 * 8);
        uint4 qv1 = *(const uint4*)(g_Qh + (size_t)tn1 * 128 + lane16 * 8);

        __half2 a0 = __hmax2(__hadd2(*(__half2*)&pv0.x, *(__half2*)&qv0.x), z);
        __half2 a1 = __hmax2(__hadd2(*(__half2*)&pv0.y, *(__half2*)&qv0.y), z);
        __half2 a2 = __hmax2(__hadd2(*(__half2*)&pv0.z, *(__half2*)&qv0.z), z);
        __half2 a3 = __hmax2(__hadd2(*(__half2*)&pv0.w, *(__half2*)&qv0.w), z);
        __half2 c0 = __hmax2(__hadd2(*(__half2*)&pv1.x, *(__half2*)&qv1.x), z);
        __half2 c1 = __hmax2(__hadd2(*(__half2*)&pv1.y, *(__half2*)&qv1.y), z);
        __half2 c2 = __hmax2(__hadd2(*(__half2*)&pv1.z, *(__half2*)&qv1.z), z);
        __half2 c3 = __hmax2(__hadd2(*(__half2*)&pv1.w, *(__half2*)&qv1.w), z);

        float2 f0 = __half22float2(a0), f1 = __half22float2(a1);
        float2 f2 = __half22float2(a2), f3 = __half22float2(a3);
        float2 g0 = __half22float2(c0), g1 = __half22float2(c1);
        float2 g2 = __half22float2(c2), g3 = __half22float2(c3);

        float p = f0.x * w2a.x;
        float q = g0.x * w2a.x;
        p = fmaf(f0.y, w2a.y, p);  q = fmaf(g0.y, w2a.y, q);
        p = fmaf(f1.x, w2a.z, p);  q = fmaf(g1.x, w2a.z, q);
        p = fmaf(f1.y, w2a.w, p);  q = fmaf(g1.y, w2a.w, q);
        p = fmaf(f2.x, w2b.x, p);  q = fmaf(g2.x, w2b.x, q);
        p = fmaf(f2.y, w2b.y, p);  q = fmaf(g2.y, w2b.y, q);
        p = fmaf(f3.x, w2b.z, p);  q = fmaf(g3.x, w2b.z, q);
        p = fmaf(f3.y, w2b.w, p);  q = fmaf(g3.y, w2b.w, q);

        #pragma unroll
        for (int o = 8; o > 0; o >>= 1) {
            p += __shfl_xor_sync(0xFFFFFFFFu, p, o);
            q += __shfl_xor_sync(0xFFFFFFFFu, q, o);
        }
        if (lane16 == 0) {
            float ex0 = expf(p + b2v);
            g_exps[e0] = ex0;
            s += ex0;
            if (has1) {
                float ex1 = expf(q + b2v);
                g_exps[e0 + 1] = ex1;
                s += ex1;
            }
        }
    }

    // ---- block reduce, last-block total, grid release (all blocks co-resident) ----
    sdata[tid] = s;
    __syncthreads();
    for (int o = 128; o > 0; o >>= 1) {
        if (tid < o) sdata[tid] += sdata[tid + o];
        __syncthreads();
    }
    if (tid == 0) {
        g_partials[blockIdx.x] = sdata[0];
        __threadfence();
        int old = atomicAdd(&g_done, 1);
        is_last = (old == EDGE_BLOCKS - 1) ? 1 : 0;
    }
    __syncthreads();
    if (is_last) {
        float t = 0.f;
        for (int i = tid; i < EDGE_BLOCKS; i += 256) t += g_partials[i];
        sdata[tid] = t;
        __syncthreads();
        for (int o = 128; o > 0; o >>= 1) {
            if (tid < o) sdata[tid] += sdata[tid + o];
            __syncthreads();
        }
        if (tid == 0) {
            g_inv_total = 1.f / sdata[0];
            __threadfence();
            atomicExch(&g_done, 0);   // release; also resets for graph replay
        }
        __syncthreads();
    } else {
        if (tid == 0) {
            while (*(volatile int*)&g_done != 0) { }
        }
        __syncthreads();
    }
    __threadfence();   // acquire g_inv_total

    // ---- fused normalize (coalesced float4 grid-stride) ----
    const float inv = *(volatile float*)&g_inv_total;
    const int n4 = E >> 2;
    for (int i = blockIdx.x * 256 + tid; i < n4; i += EDGE_BLOCKS * 256) {
        float4 v = ((const float4*)g_exps)[i];
        out4[i] = make_float4(v.x * inv, v.y * inv, v.z * inv, v.w * inv);
    }
    if (blockIdx.x == 0) {
        for (int i = (n4 << 2) + tid; i < E; i += 256)
            ((float*)out4)[i] = g_exps[i] * inv;
    }
}

extern "C" void kernel_launch(void* const* d_in, const int* in_sizes, int n_in,
                              void* d_out, int out_size) {
    const float* emb = (const float*)d_in[0];
    const int*   lm  = (const int*)d_in[1];
    const float* W1  = (const float*)d_in[2];
    const float* b1  = (const float*)d_in[3];
    const float* W2  = (const float*)d_in[4];
    const float* b2  = (const float*)d_in[5];
    float* out = (float*)d_out;
    const int E      = in_sizes[1] / 2;
    const int nodes  = in_sizes[0] / 128;
    const int ntiles = (nodes + 127) / 128;

    cudaFuncSetAttribute(k_node, cudaFuncAttributeMaxDynamicSharedMemorySize, NODE_SMEM);

    k_prep<<<128, 256>>>(W1);
    k_node<<<NODE_BLOCKS, 256, NODE_SMEM>>>(emb, b1, nodes, ntiles);
    k_edge<<<EDGE_BLOCKS, 256>>>(lm, W2, b2, (float4*)out, E);
}

// round 17
// speedup vs baseline: 1.0469x; 1.0469x over previous
#include <cuda_runtime.h>
#include <cuda_fp16.h>
#include <cstdint>

// RelationalPolicyHead, factored (R14 base + k_node A-reuse):
//   W1T fp16 pre-transposed once                      [k_prep]
//   P = emb @ U, Q = emb @ V + b1                     [k_node: persistent HMMA, one A-tile feeds both halves]
//   e_exp = exp( W2^T relu(P[src]+Q'[tgt]) + b2 )     [k_edge: pair/half-warp + fused sum]
//   probs = e_exp * (1/total)                         [k_norm]

#define EDGE_BLOCKS 2048
#define NODE_BLOCKS 296
#define MAX_NODES 100000
#define NSTR 136            // halves per smem row (272 B): conflict-free ldmatrix

__device__ __half g_Wt[2 * 128 * 128];   // [half][n][k] fp16
__device__ __half g_Ph[MAX_NODES * 128];
__device__ __half g_Qh[MAX_NODES * 128];
__device__ float  g_exps[1048576];
__device__ float  g_partials[EDGE_BLOCKS];
__device__ float  g_inv_total;
__device__ int    g_done = 0;

__device__ __forceinline__ uint32_t smem_u32(const void* p) {
    uint32_t a;
    asm("{ .reg .u64 t; cvta.to.shared.u64 t, %1; cvt.u32.u64 %0, t; }" : "=r"(a) : "l"(p));
    return a;
}

// ---------------- W1 -> fp16 transposed [h][n][k] ----------------
__global__ void k_prep(const float* __restrict__ W1) {
    int i = blockIdx.x * 256 + threadIdx.x;          // 32768
    int h = i >> 14, r = i & 16383;
    int n = r >> 7, k = r & 127;
    g_Wt[i] = __float2half_rn(W1[h * 16384 + k * 128 + n]);
}

// ---------------- node GEMM: persistent, one A-tile feeds both halves ----------------
#define AS_HALVES (128 * NSTR)
#define NODE_SMEM ((3 * AS_HALVES) * 2 + 512)   // As + Bs[2] fp16 + b1f

__global__ __launch_bounds__(256, 2)
void k_node(const float* __restrict__ emb, const float* __restrict__ b1,
            int nodes, int ntiles) {
    extern __shared__ __half hsm[];
    __half* As = hsm;                     // [m][k] 128 x NSTR
    __half* Bs = hsm + AS_HALVES;         // [h][n][k] 2 x 128 x NSTR
    float*  b1f = (float*)(hsm + 3 * AS_HALVES);

    const int tid  = threadIdx.x;
    const int lane = tid & 31;
    const int w    = tid >> 5;
    const int t0   = blockIdx.x;

    // ---- load BOTH B halves once ----
    {
        const uint4* src = (const uint4*)g_Wt;
        #pragma unroll
        for (int it = 0; it < 16; it++) {
            int i = it * 256 + tid;            // uint4 index over 2x128x16
            int r = i >> 4, c8 = (i & 15) * 8; // r spans both halves
            *(uint4*)(Bs + r * NSTR + c8) = src[i];
        }
        if (tid < 128) b1f[tid] = b1[tid];
    }

    const uint32_t as_base = smem_u32(As);
    const int bmat = lane >> 3, bs_ = lane & 7;
    const uint32_t brow_off = (uint32_t)((((bmat >> 1) * 8 + bs_) * NSTR + (bmat & 1) * 8) * 2);
    const int arow = (lane & 7) + ((lane >> 3) & 1) * 8;
    const int acol8 = (lane >> 4) * 8;

    for (int t = t0; t < ntiles; t += NODE_BLOCKS) {
        const int m0 = t * 128;

        __syncthreads();   // previous tile's ldmatrix readers done before A overwrite
        #pragma unroll
        for (int it = 0; it < 16; it++) {
            int i4 = it * 256 + tid;
            int row = i4 >> 5, c4 = (i4 & 31) * 4;
            float4 v = make_float4(0.f, 0.f, 0.f, 0.f);
            if (m0 + row < nodes) v = ((const float4*)emb)[(size_t)(m0 + row) * 32 + (i4 & 31)];
            __half2 h01 = __floats2half2_rn(v.x, v.y);
            __half2 h23 = __floats2half2_rn(v.z, v.w);
            uint2 pk;
            pk.x = *(uint32_t*)&h01; pk.y = *(uint32_t*)&h23;
            *(uint2*)(As + row * NSTR + c4) = pk;
        }
        __syncthreads();

        #pragma unroll
        for (int h = 0; h < 2; h++) {
            const uint32_t bs_base = smem_u32(Bs + h * AS_HALVES);

            float acc[16][4];
            #pragma unroll
            for (int i = 0; i < 16; i++)
                #pragma unroll
                for (int j = 0; j < 4; j++) acc[i][j] = 0.f;

            #pragma unroll
            for (int kc = 0; kc < 8; kc++) {
                uint32_t a0, a1, a2, a3;
                uint32_t aaddr = as_base + (uint32_t)(((w * 16 + arow) * NSTR) + kc * 16 + acol8) * 2u;
                asm volatile("ldmatrix.sync.aligned.m8n8.x4.shared.b16 {%0,%1,%2,%3}, [%4];"
                             : "=r"(a0), "=r"(a1), "=r"(a2), "=r"(a3) : "r"(aaddr));
                #pragma unroll
                for (int g = 0; g < 8; g++) {
                    uint32_t baddr = bs_base + brow_off + (uint32_t)(g * 16 * NSTR + kc * 16) * 2u;
                    uint32_t b0, b1r, b2, b3;
                    asm volatile("ldmatrix.sync.aligned.m8n8.x4.shared.b16 {%0,%1,%2,%3}, [%4];"
                                 : "=r"(b0), "=r"(b1r), "=r"(b2), "=r"(b3) : "r"(baddr));
                    asm volatile(
                        "mma.sync.aligned.m16n8k16.row.col.f32.f16.f16.f32 "
                        "{%0,%1,%2,%3}, {%4,%5,%6,%7}, {%8,%9}, {%0,%1,%2,%3};"
                        : "+f"(acc[2*g][0]), "+f"(acc[2*g][1]), "+f"(acc[2*g][2]), "+f"(acc[2*g][3])
                        : "r"(a0), "r"(a1), "r"(a2), "r"(a3), "r"(b0), "r"(b1r));
                    asm volatile(
                        "mma.sync.aligned.m16n8k16.row.col.f32.f16.f16.f32 "
                        "{%0,%1,%2,%3}, {%4,%5,%6,%7}, {%8,%9}, {%0,%1,%2,%3};"
                        : "+f"(acc[2*g+1][0]), "+f"(acc[2*g+1][1]), "+f"(acc[2*g+1][2]), "+f"(acc[2*g+1][3])
                        : "r"(a0), "r"(a1), "r"(a2), "r"(a3), "r"(b2), "r"(b3));
                }
            }

            __half* out = h ? g_Qh : g_Ph;
            const int r0 = m0 + w * 16 + (lane >> 2);
            const int cb = (lane & 3) * 2;
            if (r0 < nodes) {
                #pragma unroll
                for (int n8 = 0; n8 < 16; n8++) {
                    float bx = h ? b1f[n8 * 8 + cb] : 0.f;
                    float by2 = h ? b1f[n8 * 8 + cb + 1] : 0.f;
                    __half2 hv = __floats2half2_rn(acc[n8][0] + bx, acc[n8][1] + by2);
                    *(uint32_t*)(out + (size_t)r0 * 128 + n8 * 8 + cb) = *(uint32_t*)&hv;
                }
            }
            if (r0 + 8 < nodes) {
                #pragma unroll
                for (int n8 = 0; n8 < 16; n8++) {
                    float bx = h ? b1f[n8 * 8 + cb] : 0.f;
                    float by2 = h ? b1f[n8 * 8 + cb + 1] : 0.f;
                    __half2 hv = __floats2half2_rn(acc[n8][2] + bx, acc[n8][3] + by2);
                    *(uint32_t*)(out + (size_t)(r0 + 8) * 128 + n8 * 8 + cb) = *(uint32_t*)&hv;
                }
            }
        }
    }
}

// ---------------- edge kernel: half-warp per edge PAIR, fused exp + sum ----------------
__global__ __launch_bounds__(256)
void k_edge(const int* __restrict__ lm, const float* __restrict__ W2,
            const float* __restrict__ b2, int E) {
    __shared__ float sdata[256];
    __shared__ int   is_last;
    const int lane   = threadIdx.x & 31;
    const int lane16 = lane & 15;
    const int hw     = ((blockIdx.x * 256 + threadIdx.x) >> 5) * 2 + (lane >> 4);
    const int nhw    = (EDGE_BLOCKS * 256) >> 4;

    const float4 w2a = ((const float4*)W2)[lane16 * 2];
    const float4 w2b = ((const float4*)W2)[lane16 * 2 + 1];
    const float  b2v = b2[0];
    const __half2 z  = __float2half2_rn(0.f);

    const int npairs = (E + 1) >> 1;
    float s = 0.f;
    for (int pi = hw; pi < npairs; pi += nhw) {
        const int e0 = pi * 2;
        const bool has1 = (e0 + 1) < E;

        int sn0 = lm[e0];
        int tn0 = lm[E + e0];
        int sn1 = has1 ? lm[e0 + 1] : sn0;
        int tn1 = has1 ? lm[E + e0 + 1] : tn0;

        uint4 pv0 = *(const uint4*)(g_Ph + (size_t)sn0 * 128 + lane16 * 8);
        uint4 qv0 = *(const uint4*)(g_Qh + (size_t)tn0 * 128 + lane16 * 8);
        uint4 pv1 = *(const uint4*)(g_Ph + (size_t)sn1 * 128 + lane16 * 8);
        uint4 qv1 = *(const uint4*)(g_Qh + (size_t)tn1 * 128 + lane16 * 8);

        __half2 a0 = __hmax2(__hadd2(*(__half2*)&pv0.x, *(__half2*)&qv0.x), z);
        __half2 a1 = __hmax2(__hadd2(*(__half2*)&pv0.y, *(__half2*)&qv0.y), z);
        __half2 a2 = __hmax2(__hadd2(*(__half2*)&pv0.z, *(__half2*)&qv0.z), z);
        __half2 a3 = __hmax2(__hadd2(*(__half2*)&pv0.w, *(__half2*)&qv0.w), z);
        __half2 c0 = __hmax2(__hadd2(*(__half2*)&pv1.x, *(__half2*)&qv1.x), z);
        __half2 c1 = __hmax2(__hadd2(*(__half2*)&pv1.y, *(__half2*)&qv1.y), z);
        __half2 c2 = __hmax2(__hadd2(*(__half2*)&pv1.z, *(__half2*)&qv1.z), z);
        __half2 c3 = __hmax2(__hadd2(*(__half2*)&pv1.w, *(__half2*)&qv1.w), z);

        float2 f0 = __half22float2(a0), f1 = __half22float2(a1);
        float2 f2 = __half22float2(a2), f3 = __half22float2(a3);
        float2 g0 = __half22float2(c0), g1 = __half22float2(c1);
        float2 g2 = __half22float2(c2), g3 = __half22float2(c3);

        float p = f0.x * w2a.x;
        float q = g0.x * w2a.x;
        p = fmaf(f0.y, w2a.y, p);  q = fmaf(g0.y, w2a.y, q);
        p = fmaf(f1.x, w2a.z, p);  q = fmaf(g1.x, w2a.z, q);
        p = fmaf(f1.y, w2a.w, p);  q = fmaf(g1.y, w2a.w, q);
        p = fmaf(f2.x, w2b.x, p);  q = fmaf(g2.x, w2b.x, q);
        p = fmaf(f2.y, w2b.y, p);  q = fmaf(g2.y, w2b.y, q);
        p = fmaf(f3.x, w2b.z, p);  q = fmaf(g3.x, w2b.z, q);
        p = fmaf(f3.y, w2b.w, p);  q = fmaf(g3.y, w2b.w, q);

        #pragma unroll
        for (int o = 8; o > 0; o >>= 1) {
            p += __shfl_xor_sync(0xFFFFFFFFu, p, o);
            q += __shfl_xor_sync(0xFFFFFFFFu, q, o);
        }
        if (lane16 == 0) {
            float ex0 = expf(p + b2v);
            g_exps[e0] = ex0;
            s += ex0;
            if (has1) {
                float ex1 = expf(q + b2v);
                g_exps[e0 + 1] = ex1;
                s += ex1;
            }
        }
    }

    sdata[threadIdx.x] = s;
    __syncthreads();
    for (int o = 128; o > 0; o >>= 1) {
        if (threadIdx.x < o) sdata[threadIdx.x] += sdata[threadIdx.x + o];
        __syncthreads();
    }
    if (threadIdx.x == 0) {
        g_partials[blockIdx.x] = sdata[0];
        __threadfence();
        int old = atomicAdd(&g_done, 1);
        is_last = (old == EDGE_BLOCKS - 1) ? 1 : 0;
    }
    __syncthreads();
    if (is_last) {
        float t = 0.f;
        for (int i = threadIdx.x; i < EDGE_BLOCKS; i += 256) t += g_partials[i];
        sdata[threadIdx.x] = t;
        __syncthreads();
        for (int o = 128; o > 0; o >>= 1) {
            if (threadIdx.x < o) sdata[threadIdx.x] += sdata[threadIdx.x + o];
            __syncthreads();
        }
        if (threadIdx.x == 0) {
            g_inv_total = 1.f / sdata[0];
            g_done = 0;   // reset for graph replay
        }
    }
}

__global__ void k_norm(float4* __restrict__ out, int n4) {
    int i = blockIdx.x * blockDim.x + threadIdx.x;
    if (i < n4) {
        float inv = g_inv_total;
        float4 v = ((const float4*)g_exps)[i];
        out[i] = make_float4(v.x * inv, v.y * inv, v.z * inv, v.w * inv);
    }
}
__global__ void k_norm_tail(float* __restrict__ out, int start, int E) {
    int i = start + blockIdx.x * blockDim.x + threadIdx.x;
    if (i < E) out[i] = g_exps[i] * g_inv_total;
}

extern "C" void kernel_launch(void* const* d_in, const int* in_sizes, int n_in,
                              void* d_out, int out_size) {
    const float* emb = (const float*)d_in[0];
    const int*   lm  = (const int*)d_in[1];
    const float* W1  = (const float*)d_in[2];
    const float* b1  = (const float*)d_in[3];
    const float* W2  = (const float*)d_in[4];
    const float* b2  = (const float*)d_in[5];
    float* out = (float*)d_out;
    const int E      = in_sizes[1] / 2;
    const int nodes  = in_sizes[0] / 128;
    const int ntiles = (nodes + 127) / 128;

    cudaFuncSetAttribute(k_node, cudaFuncAttributeMaxDynamicSharedMemorySize, NODE_SMEM);

    k_prep<<<128, 256>>>(W1);
    k_node<<<NODE_BLOCKS, 256, NODE_SMEM>>>(emb, b1, nodes, ntiles);
    k_edge<<<EDGE_BLOCKS, 256>>>(lm, W2, b2, E);
    const int n4 = E >> 2;
    if (n4 > 0) k_norm<<<(n4 + 255) / 256, 256>>>((float4*)out, n4);
    if (E & 3) k_norm_tail<<<1, 256>>>(out, n4 << 2, E);
}